// round 1
// baseline (speedup 1.0000x reference)
#include <cuda_runtime.h>
#include <cuda_bf16.h>
#include <cstdint>

// Block-sparse batched linear:
//   Y[i] = sum_{k: i_idx[k]==i} ( X[j_idx[k]] @ W[k] + b[k] )
// X: [12][8192][256] f32, W: [48][256][256] f32, b: [48][256] f32, Y: [12][8192][256] f32
//
// Strategy: per-output-block GEMM with bf16 hi/lo split (3x mma.sync.m16n8k16.bf16),
// fp32 accumulation. CTA tile 128x128, BK=32, 256 threads (8 warps = 2x4, 64x32 each).

namespace {

constexpr int NBLK   = 12;
constexpr int DDIM   = 256;
constexpr int BATCHN = 8192;
constexpr int NACT   = 48;

constexpr int BM = 128;
constexpr int BN = 128;
constexpr int BK = 32;
constexpr int ST = 40;           // smem row stride in bf16 elems (32 data + 8 pad) -> conflict-free
constexpr int THREADS = 256;

__device__ __forceinline__ uint32_t lds32(const __nv_bfloat16* p) {
    return *reinterpret_cast<const uint32_t*>(p);
}

__device__ __forceinline__ void mma_bf16(float d[4], const uint32_t a[4], const uint32_t b[2]) {
    asm volatile(
        "mma.sync.aligned.m16n8k16.row.col.f32.bf16.bf16.f32 "
        "{%0,%1,%2,%3}, {%4,%5,%6,%7}, {%8,%9}, {%0,%1,%2,%3};\n"
        : "+f"(d[0]), "+f"(d[1]), "+f"(d[2]), "+f"(d[3])
        : "r"(a[0]), "r"(a[1]), "r"(a[2]), "r"(a[3]),
          "r"(b[0]), "r"(b[1]));
}

// Split two fp32 values into packed bf16x2 hi and lo parts (x ~= hi + lo).
__device__ __forceinline__ void split2(float x, float y, uint32_t& hi, uint32_t& lo) {
    __nv_bfloat16 hx = __float2bfloat16_rn(x);
    __nv_bfloat16 hy = __float2bfloat16_rn(y);
    __nv_bfloat16 lx = __float2bfloat16_rn(x - __bfloat162float(hx));
    __nv_bfloat16 ly = __float2bfloat16_rn(y - __bfloat162float(hy));
    __nv_bfloat162 hp = __halves2bfloat162(hx, hy);
    __nv_bfloat162 lp = __halves2bfloat162(lx, ly);
    hi = *reinterpret_cast<uint32_t*>(&hp);
    lo = *reinterpret_cast<uint32_t*>(&lp);
}

__global__ void __launch_bounds__(THREADS)
bs_linear_kernel(const float* __restrict__ X,
                 const float* __restrict__ W,
                 const float* __restrict__ Bv,
                 const int*   __restrict__ i_idx,
                 const int*   __restrict__ j_idx,
                 float*       __restrict__ Y)
{
    // smem: A_hi | A_lo | B_hi | B_lo, each BM(or BN)*ST bf16 = 5120 elems
    __shared__ __align__(16) __nv_bfloat16 smem[4 * BM * ST];
    __nv_bfloat16* AsH = smem;
    __nv_bfloat16* AsL = smem + 1 * BM * ST;
    __nv_bfloat16* BsH = smem + 2 * BM * ST;   // stored transposed: [n][k]
    __nv_bfloat16* BsL = smem + 3 * BM * ST;

    const int tid    = threadIdx.x;
    const int wid    = tid >> 5;
    const int lane   = tid & 31;
    const int g      = lane >> 2;    // group id 0..7
    const int tg     = lane & 3;     // thread-in-group 0..3
    const int warp_m = wid >> 2;     // 0..1  (64 rows each)
    const int warp_n = wid & 3;      // 0..3  (32 cols each)

    const int m0 = blockIdx.x * BM;
    const int n0 = blockIdx.y * BN;
    const int ib = blockIdx.z;

    float acc[4][4][4];
    #pragma unroll
    for (int mt = 0; mt < 4; ++mt)
        #pragma unroll
        for (int nt = 0; nt < 4; ++nt)
            #pragma unroll
            for (int q = 0; q < 4; ++q)
                acc[mt][nt][q] = 0.0f;

    for (int k = 0; k < NACT; ++k) {
        if (__ldg(&i_idx[k]) != ib) continue;
        const float* Xg = X + (size_t)__ldg(&j_idx[k]) * BATCHN * DDIM;
        const float* Wk = W + (size_t)k * DDIM * DDIM;

        for (int kk = 0; kk < DDIM; kk += BK) {
            // ---- load A tile: 128 rows x 32 k-cols of X, split to hi/lo bf16
            #pragma unroll
            for (int t = 0; t < 4; ++t) {
                int s   = tid + t * THREADS;      // 0..1023 float4 slots
                int row = s >> 3;                 // 8 float4 per row
                int col = (s & 7) << 2;
                const float4 v = *reinterpret_cast<const float4*>(
                    Xg + (size_t)(m0 + row) * DDIM + kk + col);
                uint32_t h01, l01, h23, l23;
                split2(v.x, v.y, h01, l01);
                split2(v.z, v.w, h23, l23);
                *reinterpret_cast<uint32_t*>(&AsH[row * ST + col])     = h01;
                *reinterpret_cast<uint32_t*>(&AsH[row * ST + col + 2]) = h23;
                *reinterpret_cast<uint32_t*>(&AsL[row * ST + col])     = l01;
                *reinterpret_cast<uint32_t*>(&AsL[row * ST + col + 2]) = l23;
            }
            // ---- load B tile: 32 k-rows x 128 n-cols of W, store transposed [n][k]
            #pragma unroll
            for (int t = 0; t < 4; ++t) {
                int s = tid + t * THREADS;        // 0..1023 float4 slots
                int r = s >> 5;                   // k row 0..31 (32 float4 per row)
                int c = (s & 31) << 2;            // n col
                const float4 v = *reinterpret_cast<const float4*>(
                    Wk + (size_t)(kk + r) * DDIM + n0 + c);
                float f[4] = {v.x, v.y, v.z, v.w};
                #pragma unroll
                for (int q = 0; q < 4; ++q) {
                    __nv_bfloat16 h = __float2bfloat16_rn(f[q]);
                    BsH[(c + q) * ST + r] = h;
                    BsL[(c + q) * ST + r] =
                        __float2bfloat16_rn(f[q] - __bfloat162float(h));
                }
            }
            __syncthreads();

            // ---- compute: two k16 steps per BK
            #pragma unroll
            for (int ks = 0; ks < BK; ks += 16) {
                uint32_t ah[4][4], al[4][4], bh[4][2], bl[4][2];
                #pragma unroll
                for (int mt = 0; mt < 4; ++mt) {
                    int rb = warp_m * 64 + mt * 16;
                    int o0 = (rb + g)     * ST + ks + tg * 2;
                    int o1 = (rb + g + 8) * ST + ks + tg * 2;
                    ah[mt][0] = lds32(AsH + o0);
                    ah[mt][1] = lds32(AsH + o1);
                    ah[mt][2] = lds32(AsH + o0 + 8);
                    ah[mt][3] = lds32(AsH + o1 + 8);
                    al[mt][0] = lds32(AsL + o0);
                    al[mt][1] = lds32(AsL + o1);
                    al[mt][2] = lds32(AsL + o0 + 8);
                    al[mt][3] = lds32(AsL + o1 + 8);
                }
                #pragma unroll
                for (int nt = 0; nt < 4; ++nt) {
                    int n = warp_n * 32 + nt * 8 + g;
                    int o = n * ST + ks + tg * 2;
                    bh[nt][0] = lds32(BsH + o);
                    bh[nt][1] = lds32(BsH + o + 8);
                    bl[nt][0] = lds32(BsL + o);
                    bl[nt][1] = lds32(BsL + o + 8);
                }
                #pragma unroll
                for (int mt = 0; mt < 4; ++mt)
                    #pragma unroll
                    for (int nt = 0; nt < 4; ++nt) {
                        mma_bf16(acc[mt][nt], ah[mt], bh[nt]);  // hi*hi
                        mma_bf16(acc[mt][nt], ah[mt], bl[nt]);  // hi*lo
                        mma_bf16(acc[mt][nt], al[mt], bh[nt]);  // lo*hi
                    }
            }
            __syncthreads();
        }

        // ---- bias for this active block (added once per block)
        #pragma unroll
        for (int nt = 0; nt < 4; ++nt) {
            int col  = n0 + warp_n * 32 + nt * 8 + tg * 2;
            float b0 = __ldg(&Bv[k * DDIM + col]);
            float b1 = __ldg(&Bv[k * DDIM + col + 1]);
            #pragma unroll
            for (int mt = 0; mt < 4; ++mt) {
                acc[mt][nt][0] += b0;
                acc[mt][nt][1] += b1;
                acc[mt][nt][2] += b0;
                acc[mt][nt][3] += b1;
            }
        }
    }

    // ---- epilogue: every (ib, row, col) written exactly once; rows with no
    // active blocks get zeros (matches segment_sum semantics).
    #pragma unroll
    for (int mt = 0; mt < 4; ++mt) {
        int row = m0 + warp_m * 64 + mt * 16 + g;
        #pragma unroll
        for (int nt = 0; nt < 4; ++nt) {
            int col = n0 + warp_n * 32 + nt * 8 + tg * 2;
            size_t o0 = ((size_t)ib * BATCHN + row) * DDIM + col;
            size_t o1 = o0 + (size_t)8 * DDIM;
            *reinterpret_cast<float2*>(Y + o0) = make_float2(acc[mt][nt][0], acc[mt][nt][1]);
            *reinterpret_cast<float2*>(Y + o1) = make_float2(acc[mt][nt][2], acc[mt][nt][3]);
        }
    }
}

} // namespace

extern "C" void kernel_launch(void* const* d_in, const int* in_sizes, int n_in,
                              void* d_out, int out_size) {
    const float* X     = (const float*)d_in[0];
    const float* W     = (const float*)d_in[1];
    const float* b     = (const float*)d_in[2];
    const int*   i_idx = (const int*)d_in[3];
    const int*   j_idx = (const int*)d_in[4];
    float*       Y     = (float*)d_out;

    dim3 grid(BATCHN / BM, DDIM / BN, NBLK);   // 64 x 2 x 12 = 1536 CTAs
    bs_linear_kernel<<<grid, THREADS>>>(X, W, b, i_idx, j_idx, Y);
}

// round 3
// speedup vs baseline: 1.3475x; 1.3475x over previous
#include <cuda_runtime.h>
#include <cuda_bf16.h>
#include <cstdint>

// Block-sparse batched linear (sm_103 family-safe: mma.sync + ldmatrix):
//   Y[i] = sum_{k: i_idx[k]==i} ( X[j_idx[k]] @ W[k] + b[k] )
// Prep: X -> bf16 hi/lo; W -> transposed [n][k] bf16 hi/lo.
// Main: CTA 128x128, BK=32, 8 warps (2x4, 64x32 warp tiles), 3-pass bf16
// hi/lo split mma.sync.m16n8k16, ldmatrix.x4 fragment feeds, cp.async
// 2-stage pipeline, 2 CTAs/SM.

namespace {

constexpr int NBLK   = 12;
constexpr int DDIM   = 256;
constexpr int BATCHN = 8192;
constexpr int NACT   = 48;

constexpr int BM = 128;
constexpr int BN = 128;
constexpr int BK = 32;
constexpr int NCH = 32;          // 4 active blocks * 8 k-chunks
constexpr int THREADS = 256;

constexpr uint32_t ROWB   = 80;          // 64B data + 16B pad per 32-elem row
constexpr uint32_t ASZ    = 128 * ROWB;  // 10240 B per operand array
constexpr uint32_t OFF_AH = 0;
constexpr uint32_t OFF_AL = ASZ;
constexpr uint32_t OFF_BH = 2 * ASZ;
constexpr uint32_t OFF_BL = 3 * ASZ;
constexpr uint32_t STAGE_BYTES = 4 * ASZ;               // 40960
constexpr uint32_t SM_BIAS     = 2 * STAGE_BYTES;       // 81920
constexpr uint32_t SMEM_TOTAL  = SM_BIAS + 128 * 4;     // 82432

// ---- device scratch (static; no runtime allocation) ----
__device__ __nv_bfloat16 g_Xh[(size_t)NBLK * BATCHN * DDIM];
__device__ __nv_bfloat16 g_Xl[(size_t)NBLK * BATCHN * DDIM];
__device__ __nv_bfloat16 g_Wth[(size_t)NACT * DDIM * DDIM];   // [blk][n][k]
__device__ __nv_bfloat16 g_Wtl[(size_t)NACT * DDIM * DDIM];

// ---------------- helpers ----------------
__device__ __forceinline__ uint32_t smem_u32(const void* p) {
    uint32_t a;
    asm("{ .reg .u64 t; cvta.to.shared.u64 t, %1; cvt.u32.u64 %0, t; }"
        : "=r"(a) : "l"(p));
    return a;
}
__device__ __forceinline__ void cp16(uint32_t dst, const void* src) {
    asm volatile("cp.async.cg.shared.global [%0], [%1], 16;\n" :: "r"(dst), "l"(src));
}
__device__ __forceinline__ void cp_commit() { asm volatile("cp.async.commit_group;\n"); }
template <int N>
__device__ __forceinline__ void cp_wait() { asm volatile("cp.async.wait_group %0;\n" :: "n"(N)); }

__device__ __forceinline__ void ldsm4(uint32_t r[4], uint32_t addr) {
    asm volatile("ldmatrix.sync.aligned.m8n8.x4.shared.b16 {%0,%1,%2,%3}, [%4];"
                 : "=r"(r[0]), "=r"(r[1]), "=r"(r[2]), "=r"(r[3]) : "r"(addr));
}
__device__ __forceinline__ void mma_bf16(float d[4], const uint32_t a[4],
                                         uint32_t b0, uint32_t b1) {
    asm volatile(
        "mma.sync.aligned.m16n8k16.row.col.f32.bf16.bf16.f32 "
        "{%0,%1,%2,%3}, {%4,%5,%6,%7}, {%8,%9}, {%0,%1,%2,%3};\n"
        : "+f"(d[0]), "+f"(d[1]), "+f"(d[2]), "+f"(d[3])
        : "r"(a[0]), "r"(a[1]), "r"(a[2]), "r"(a[3]), "r"(b0), "r"(b1));
}

__device__ __forceinline__ void split_pack(float x, float y, uint32_t& hi, uint32_t& lo) {
    __nv_bfloat16 hx = __float2bfloat16_rn(x);
    __nv_bfloat16 hy = __float2bfloat16_rn(y);
    __nv_bfloat16 lx = __float2bfloat16_rn(x - __bfloat162float(hx));
    __nv_bfloat16 ly = __float2bfloat16_rn(y - __bfloat162float(hy));
    __nv_bfloat162 hp = __halves2bfloat162(hx, hy);
    __nv_bfloat162 lp = __halves2bfloat162(lx, ly);
    hi = *reinterpret_cast<uint32_t*>(&hp);
    lo = *reinterpret_cast<uint32_t*>(&lp);
}

// ---------------- prep kernels ----------------
__global__ void __launch_bounds__(256) conv_x_kernel(const float* __restrict__ X) {
    size_t i = (size_t)blockIdx.x * blockDim.x + threadIdx.x;  // float4 slot
    const float4 v = reinterpret_cast<const float4*>(X)[i];
    uint32_t h01, l01, h23, l23;
    split_pack(v.x, v.y, h01, l01);
    split_pack(v.z, v.w, h23, l23);
    reinterpret_cast<uint2*>(g_Xh)[i] = make_uint2(h01, h23);
    reinterpret_cast<uint2*>(g_Xl)[i] = make_uint2(l01, l23);
}

__global__ void __launch_bounds__(1024) conv_w_kernel(const float* __restrict__ W) {
    __shared__ float t[32][33];
    const int blk = blockIdx.z;
    const int n0 = blockIdx.x * 32;
    const int k0 = blockIdx.y * 32;
    const int x = threadIdx.x, y = threadIdx.y;
    t[y][x] = W[((size_t)blk * DDIM + k0 + y) * DDIM + n0 + x];
    __syncthreads();
    const float v = t[x][y];   // = W[k0+x][n0+y]
    __nv_bfloat16 h = __float2bfloat16_rn(v);
    __nv_bfloat16 l = __float2bfloat16_rn(v - __bfloat162float(h));
    const size_t o = ((size_t)blk * DDIM + (n0 + y)) * DDIM + (k0 + x);
    g_Wth[o] = h;
    g_Wtl[o] = l;
}

// ---------------- main kernel ----------------
__device__ __forceinline__ void load_chunk(
    uint32_t stage_base, int tid,
    const __nv_bfloat16* Ah, const __nv_bfloat16* Al,
    const __nv_bfloat16* Bh, const __nv_bfloat16* Bl)
{
    #pragma unroll
    for (int t = 0; t < 2; ++t) {
        const int slot = tid + t * THREADS;       // 0..511
        const int row  = slot >> 2;               // 0..127
        const int c16  = slot & 3;                // 16B chunk within 64B row
        const uint32_t dst = (uint32_t)row * ROWB + (uint32_t)c16 * 16;
        const size_t   so  = (size_t)row * DDIM + c16 * 8;
        cp16(stage_base + OFF_AH + dst, Ah + so);
        cp16(stage_base + OFF_AL + dst, Al + so);
        cp16(stage_base + OFF_BH + dst, Bh + so);
        cp16(stage_base + OFF_BL + dst, Bl + so);
    }
}

__global__ void __launch_bounds__(THREADS, 2)
bs_mma_kernel(const float* __restrict__ Bv,
              const int*   __restrict__ i_idx,
              const int*   __restrict__ j_idx,
              float*       __restrict__ Y)
{
    extern __shared__ __align__(128) char smem[];
    const uint32_t sb = smem_u32(smem);

    const int tid    = threadIdx.x;
    const int wid    = tid >> 5;
    const int lane   = tid & 31;
    const int g      = lane >> 2;
    const int tg     = lane & 3;
    const int warp_m = wid >> 2;     // 0..1
    const int warp_n = wid & 3;      // 0..3
    const int lrow   = lane & 15;    // ldmatrix row within 16
    const int lseg   = lane >> 4;    // ldmatrix 16B segment

    const int m0 = blockIdx.x * BM;
    const int n0 = blockIdx.y * BN;
    const int ib = blockIdx.z;

    // active blocks feeding output row ib (exactly 4)
    int kact[4], jact[4];
    {
        int na = 0;
        #pragma unroll 1
        for (int k = 0; k < NACT; ++k) {
            if (__ldg(i_idx + k) == ib) {
                if (na < 4) { kact[na] = k; jact[na] = __ldg(j_idx + k); }
                ++na;
            }
        }
    }

    float acc[4][4][4];
    #pragma unroll
    for (int mt = 0; mt < 4; ++mt)
        #pragma unroll
        for (int nt = 0; nt < 4; ++nt)
            #pragma unroll
            for (int q = 0; q < 4; ++q)
                acc[mt][nt][q] = 0.0f;

    auto chunk_srcs = [&](int c, const __nv_bfloat16*& Ah, const __nv_bfloat16*& Al,
                          const __nv_bfloat16*& Bh, const __nv_bfloat16*& Bl) {
        const int a  = c >> 3;
        const int kk = (c & 7) * BK;
        const size_t abase = ((size_t)jact[a] * BATCHN + m0) * DDIM + kk;
        Ah = g_Xh + abase;
        Al = g_Xl + abase;
        const size_t bbase = ((size_t)kact[a] * DDIM + n0) * DDIM + kk;
        Bh = g_Wth + bbase;
        Bl = g_Wtl + bbase;
    };

    {   // prologue
        const __nv_bfloat16 *Ah, *Al, *Bh, *Bl;
        chunk_srcs(0, Ah, Al, Bh, Bl);
        load_chunk(sb, tid, Ah, Al, Bh, Bl);
        cp_commit();
    }

    for (int c = 0; c < NCH; ++c) {
        if (c + 1 < NCH) {
            const __nv_bfloat16 *Ah, *Al, *Bh, *Bl;
            chunk_srcs(c + 1, Ah, Al, Bh, Bl);
            load_chunk(sb + (uint32_t)((c + 1) & 1) * STAGE_BYTES, tid, Ah, Al, Bh, Bl);
            cp_commit();
            cp_wait<1>();
        } else {
            cp_wait<0>();
        }
        __syncthreads();

        const uint32_t st = sb + (uint32_t)(c & 1) * STAGE_BYTES;
        const uint32_t aHb = st + OFF_AH, aLb = st + OFF_AL;
        const uint32_t bHb = st + OFF_BH, bLb = st + OFF_BL;

        #pragma unroll
        for (int ks = 0; ks < BK; ks += 16) {
            const uint32_t fcol = (uint32_t)(ks * 2 + lseg * 16);
            // B fragments: two 16-n halves of the 32-n warp tile, hi & lo
            const uint32_t bo = (uint32_t)(warp_n * 32 + lrow) * ROWB + fcol;
            uint32_t bh0[4], bh1[4], bl0[4], bl1[4];
            ldsm4(bh0, bHb + bo);
            ldsm4(bh1, bHb + bo + 16 * ROWB);
            ldsm4(bl0, bLb + bo);
            ldsm4(bl1, bLb + bo + 16 * ROWB);

            #pragma unroll
            for (int mt = 0; mt < 4; ++mt) {
                const uint32_t ao =
                    (uint32_t)(warp_m * 64 + mt * 16 + lrow) * ROWB + fcol;
                uint32_t ah[4], al[4];
                ldsm4(ah, aHb + ao);
                ldsm4(al, aLb + ao);
                // nt 0..3: half h = nt>>1, sub s = nt&1 -> b regs {b[s], b[s+2]}
                mma_bf16(acc[mt][0], ah, bh0[0], bh0[2]);
                mma_bf16(acc[mt][0], ah, bl0[0], bl0[2]);
                mma_bf16(acc[mt][0], al, bh0[0], bh0[2]);

                mma_bf16(acc[mt][1], ah, bh0[1], bh0[3]);
                mma_bf16(acc[mt][1], ah, bl0[1], bl0[3]);
                mma_bf16(acc[mt][1], al, bh0[1], bh0[3]);

                mma_bf16(acc[mt][2], ah, bh1[0], bh1[2]);
                mma_bf16(acc[mt][2], ah, bl1[0], bl1[2]);
                mma_bf16(acc[mt][2], al, bh1[0], bh1[2]);

                mma_bf16(acc[mt][3], ah, bh1[1], bh1[3]);
                mma_bf16(acc[mt][3], ah, bl1[1], bl1[3]);
                mma_bf16(acc[mt][3], al, bh1[1], bh1[3]);
            }
        }
        __syncthreads();
    }

    // bias sums for this CTA's 128 output cols
    if (tid < BN) {
        const int col = n0 + tid;
        float bs = __ldg(Bv + (size_t)kact[0] * DDIM + col)
                 + __ldg(Bv + (size_t)kact[1] * DDIM + col)
                 + __ldg(Bv + (size_t)kact[2] * DDIM + col)
                 + __ldg(Bv + (size_t)kact[3] * DDIM + col);
        reinterpret_cast<float*>(smem + SM_BIAS)[tid] = bs;
    }
    __syncthreads();
    const float* biasp = reinterpret_cast<const float*>(smem + SM_BIAS);

    // epilogue: each element written exactly once
    #pragma unroll
    for (int mt = 0; mt < 4; ++mt) {
        const int row = m0 + warp_m * 64 + mt * 16 + g;
        #pragma unroll
        for (int nt = 0; nt < 4; ++nt) {
            const int lc  = warp_n * 32 + nt * 8 + tg * 2;
            const float b0 = biasp[lc], b1 = biasp[lc + 1];
            const size_t o0 = ((size_t)ib * BATCHN + row) * DDIM + n0 + lc;
            const size_t o1 = o0 + (size_t)8 * DDIM;
            *reinterpret_cast<float2*>(Y + o0) =
                make_float2(acc[mt][nt][0] + b0, acc[mt][nt][1] + b1);
            *reinterpret_cast<float2*>(Y + o1) =
                make_float2(acc[mt][nt][2] + b0, acc[mt][nt][3] + b1);
        }
    }
}

} // namespace

extern "C" void kernel_launch(void* const* d_in, const int* in_sizes, int n_in,
                              void* d_out, int out_size) {
    const float* X     = (const float*)d_in[0];
    const float* W     = (const float*)d_in[1];
    const float* b     = (const float*)d_in[2];
    const int*   i_idx = (const int*)d_in[3];
    const int*   j_idx = (const int*)d_in[4];
    float*       Y     = (float*)d_out;

    cudaFuncSetAttribute(bs_mma_kernel,
                         cudaFuncAttributeMaxDynamicSharedMemorySize, SMEM_TOTAL);

    const int x4 = NBLK * BATCHN * DDIM / 4;
    conv_x_kernel<<<x4 / 256, 256>>>(X);
    conv_w_kernel<<<dim3(DDIM / 32, DDIM / 32, NACT), dim3(32, 32)>>>(W);

    bs_mma_kernel<<<dim3(BATCHN / BM, DDIM / BN, NBLK), THREADS, SMEM_TOTAL>>>(
        b, i_idx, j_idx, Y);
}

// round 4
// speedup vs baseline: 4.4530x; 3.3047x over previous
#include <cuda_runtime.h>
#include <cuda_fp16.h>
#include <cstdint>

// Block-sparse batched linear (sm_103 family-safe: mma.sync + ldmatrix):
//   Y[i] = sum_{k: i_idx[k]==i} ( X[j_idx[k]] @ W[k] + b[k] )
// Prep: X -> fp16; W -> transposed [n][k] fp16.
// Main: CTA 128x128, BK=32, 8 warps (2x4, 64x32 warp tiles), single-pass
// fp16 mma.sync.m16n8k16 with f32 accum, ldmatrix.x4 feeds, 4-stage
// cp.async pipeline, 2 CTAs/SM.

namespace {

constexpr int NBLK   = 12;
constexpr int DDIM   = 256;
constexpr int BATCHN = 8192;
constexpr int NACT   = 48;

constexpr int BM = 128;
constexpr int BN = 128;
constexpr int BK = 32;
constexpr int NCH = 32;          // 4 active blocks * 8 k-chunks
constexpr int NSTG = 4;
constexpr int THREADS = 256;

constexpr uint32_t ROWB   = 80;          // 64B data + 16B pad per 32-elem row
constexpr uint32_t ASZ    = 128 * ROWB;  // 10240 B per operand tile
constexpr uint32_t OFF_A  = 0;
constexpr uint32_t OFF_B  = ASZ;
constexpr uint32_t STAGE_BYTES = 2 * ASZ;                  // 20480
constexpr uint32_t SM_BIAS     = NSTG * STAGE_BYTES;       // 81920
constexpr uint32_t SMEM_TOTAL  = SM_BIAS + 128 * 4;        // 82432

// ---- device scratch (static; no runtime allocation) ----
__device__ __half g_Xf[(size_t)NBLK * BATCHN * DDIM];
__device__ __half g_Wtf[(size_t)NACT * DDIM * DDIM];   // [blk][n][k]

// ---------------- helpers ----------------
__device__ __forceinline__ uint32_t smem_u32(const void* p) {
    uint32_t a;
    asm("{ .reg .u64 t; cvta.to.shared.u64 t, %1; cvt.u32.u64 %0, t; }"
        : "=r"(a) : "l"(p));
    return a;
}
__device__ __forceinline__ void cp16(uint32_t dst, const void* src) {
    asm volatile("cp.async.cg.shared.global [%0], [%1], 16;\n" :: "r"(dst), "l"(src));
}
__device__ __forceinline__ void cp_commit() { asm volatile("cp.async.commit_group;\n"); }
template <int N>
__device__ __forceinline__ void cp_wait() { asm volatile("cp.async.wait_group %0;\n" :: "n"(N)); }

__device__ __forceinline__ void ldsm4(uint32_t r[4], uint32_t addr) {
    asm volatile("ldmatrix.sync.aligned.m8n8.x4.shared.b16 {%0,%1,%2,%3}, [%4];"
                 : "=r"(r[0]), "=r"(r[1]), "=r"(r[2]), "=r"(r[3]) : "r"(addr));
}
__device__ __forceinline__ void mma_f16(float d[4], const uint32_t a[4],
                                        uint32_t b0, uint32_t b1) {
    asm volatile(
        "mma.sync.aligned.m16n8k16.row.col.f32.f16.f16.f32 "
        "{%0,%1,%2,%3}, {%4,%5,%6,%7}, {%8,%9}, {%0,%1,%2,%3};\n"
        : "+f"(d[0]), "+f"(d[1]), "+f"(d[2]), "+f"(d[3])
        : "r"(a[0]), "r"(a[1]), "r"(a[2]), "r"(a[3]), "r"(b0), "r"(b1));
}

// ---------------- prep kernels ----------------
__global__ void __launch_bounds__(256) conv_x_kernel(const float* __restrict__ X) {
    size_t i = (size_t)blockIdx.x * blockDim.x + threadIdx.x;  // float4 slot
    const float4 v = reinterpret_cast<const float4*>(X)[i];
    __half2 p0 = __floats2half2_rn(v.x, v.y);
    __half2 p1 = __floats2half2_rn(v.z, v.w);
    reinterpret_cast<uint2*>(g_Xf)[i] =
        make_uint2(*reinterpret_cast<uint32_t*>(&p0), *reinterpret_cast<uint32_t*>(&p1));
}

__global__ void __launch_bounds__(1024) conv_w_kernel(const float* __restrict__ W) {
    __shared__ float t[32][33];
    const int blk = blockIdx.z;
    const int n0 = blockIdx.x * 32;
    const int k0 = blockIdx.y * 32;
    const int x = threadIdx.x, y = threadIdx.y;
    t[y][x] = W[((size_t)blk * DDIM + k0 + y) * DDIM + n0 + x];
    __syncthreads();
    const float v = t[x][y];   // = W[k0+x][n0+y]
    g_Wtf[((size_t)blk * DDIM + (n0 + y)) * DDIM + (k0 + x)] = __float2half_rn(v);
}

// ---------------- main kernel ----------------
__device__ __forceinline__ void load_chunk(
    uint32_t stage_base, int tid, const __half* A, const __half* B)
{
    #pragma unroll
    for (int t = 0; t < 2; ++t) {
        const int slot = tid + t * THREADS;       // 0..511
        const int row  = slot >> 2;               // 0..127
        const int c16  = slot & 3;                // 16B chunk within 64B row
        const uint32_t dst = (uint32_t)row * ROWB + (uint32_t)c16 * 16;
        const size_t   so  = (size_t)row * DDIM + c16 * 8;
        cp16(stage_base + OFF_A + dst, A + so);
        cp16(stage_base + OFF_B + dst, B + so);
    }
}

__global__ void __launch_bounds__(THREADS, 2)
bs_mma_kernel(const float* __restrict__ Bv,
              const int*   __restrict__ i_idx,
              const int*   __restrict__ j_idx,
              float*       __restrict__ Y)
{
    extern __shared__ __align__(128) char smem[];
    const uint32_t sb = smem_u32(smem);

    const int tid    = threadIdx.x;
    const int wid    = tid >> 5;
    const int lane   = tid & 31;
    const int g      = lane >> 2;
    const int tg     = lane & 3;
    const int warp_m = wid >> 2;     // 0..1
    const int warp_n = wid & 3;      // 0..3
    const int lrow   = lane & 15;    // ldmatrix row within 16
    const int lseg   = lane >> 4;    // ldmatrix 16B segment

    const int m0 = blockIdx.x * BM;
    const int n0 = blockIdx.y * BN;
    const int ib = blockIdx.z;

    // active blocks feeding output row ib (exactly 4 by pattern construction)
    int kact[4], jact[4];
    {
        int na = 0;
        #pragma unroll 1
        for (int k = 0; k < NACT; ++k) {
            if (__ldg(i_idx + k) == ib) {
                if (na < 4) { kact[na] = k; jact[na] = __ldg(j_idx + k); }
                ++na;
            }
        }
    }

    float acc[4][4][4];
    #pragma unroll
    for (int mt = 0; mt < 4; ++mt)
        #pragma unroll
        for (int nt = 0; nt < 4; ++nt)
            #pragma unroll
            for (int q = 0; q < 4; ++q)
                acc[mt][nt][q] = 0.0f;

    auto chunk_srcs = [&](int c, const __half*& A, const __half*& B) {
        const int a  = c >> 3;
        const int kk = (c & 7) * BK;
        A = g_Xf  + ((size_t)jact[a] * BATCHN + m0) * DDIM + kk;
        B = g_Wtf + ((size_t)kact[a] * DDIM + n0) * DDIM + kk;
    };

    // prologue: preload NSTG-1 chunks
    #pragma unroll
    for (int c = 0; c < NSTG - 1; ++c) {
        const __half *A, *B;
        chunk_srcs(c, A, B);
        load_chunk(sb + (uint32_t)c * STAGE_BYTES, tid, A, B);
        cp_commit();
    }

    for (int c = 0; c < NCH; ++c) {
        cp_wait<NSTG - 2>();          // chunk c's data resident
        __syncthreads();              // also protects stage (c-1)%NSTG reuse below

        if (c + NSTG - 1 < NCH) {     // issue load for chunk c+3 into stage (c-1)%NSTG
            const __half *A, *B;
            chunk_srcs(c + NSTG - 1, A, B);
            load_chunk(sb + (uint32_t)((c + NSTG - 1) % NSTG) * STAGE_BYTES, tid, A, B);
            cp_commit();
        } else {
            cp_commit();              // keep group count in sync for cp_wait
        }

        const uint32_t st = sb + (uint32_t)(c % NSTG) * STAGE_BYTES;
        const uint32_t aB = st + OFF_A, bB = st + OFF_B;

        #pragma unroll
        for (int ks = 0; ks < BK; ks += 16) {
            const uint32_t fcol = (uint32_t)(ks * 2 + lseg * 16);
            const uint32_t bo = (uint32_t)(warp_n * 32 + lrow) * ROWB + fcol;
            uint32_t b0[4], b1[4];
            ldsm4(b0, bB + bo);
            ldsm4(b1, bB + bo + 16 * ROWB);

            #pragma unroll
            for (int mt = 0; mt < 4; ++mt) {
                const uint32_t ao =
                    (uint32_t)(warp_m * 64 + mt * 16 + lrow) * ROWB + fcol;
                uint32_t a[4];
                ldsm4(a, aB + ao);
                mma_f16(acc[mt][0], a, b0[0], b0[2]);
                mma_f16(acc[mt][1], a, b0[1], b0[3]);
                mma_f16(acc[mt][2], a, b1[0], b1[2]);
                mma_f16(acc[mt][3], a, b1[1], b1[3]);
            }
        }
    }

    // bias sums for this CTA's 128 output cols
    __syncthreads();
    if (tid < BN) {
        const int col = n0 + tid;
        float bs = __ldg(Bv + (size_t)kact[0] * DDIM + col)
                 + __ldg(Bv + (size_t)kact[1] * DDIM + col)
                 + __ldg(Bv + (size_t)kact[2] * DDIM + col)
                 + __ldg(Bv + (size_t)kact[3] * DDIM + col);
        reinterpret_cast<float*>(smem + SM_BIAS)[tid] = bs;
    }
    __syncthreads();
    const float* biasp = reinterpret_cast<const float*>(smem + SM_BIAS);

    // epilogue: each element written exactly once; rows with no active block
    // never appear (every ib has 4 blocks), zeros case can't arise here.
    #pragma unroll
    for (int mt = 0; mt < 4; ++mt) {
        const int row = m0 + warp_m * 64 + mt * 16 + g;
        #pragma unroll
        for (int nt = 0; nt < 4; ++nt) {
            const int lc  = warp_n * 32 + nt * 8 + tg * 2;
            const float b0 = biasp[lc], b1 = biasp[lc + 1];
            const size_t o0 = ((size_t)ib * BATCHN + row) * DDIM + n0 + lc;
            const size_t o1 = o0 + (size_t)8 * DDIM;
            *reinterpret_cast<float2*>(Y + o0) =
                make_float2(acc[mt][nt][0] + b0, acc[mt][nt][1] + b1);
            *reinterpret_cast<float2*>(Y + o1) =
                make_float2(acc[mt][nt][2] + b0, acc[mt][nt][3] + b1);
        }
    }
}

} // namespace

extern "C" void kernel_launch(void* const* d_in, const int* in_sizes, int n_in,
                              void* d_out, int out_size) {
    const float* X     = (const float*)d_in[0];
    const float* W     = (const float*)d_in[1];
    const float* b     = (const float*)d_in[2];
    const int*   i_idx = (const int*)d_in[3];
    const int*   j_idx = (const int*)d_in[4];
    float*       Y     = (float*)d_out;

    cudaFuncSetAttribute(bs_mma_kernel,
                         cudaFuncAttributeMaxDynamicSharedMemorySize, SMEM_TOTAL);

    const int x4 = NBLK * BATCHN * DDIM / 4;
    conv_x_kernel<<<x4 / 256, 256>>>(X);
    conv_w_kernel<<<dim3(DDIM / 32, DDIM / 32, NACT), dim3(32, 32)>>>(W);

    bs_mma_kernel<<<dim3(BATCHN / BM, DDIM / BN, NBLK), THREADS, SMEM_TOTAL>>>(
        b, i_idx, j_idx, Y);
}